// round 16
// baseline (speedup 1.0000x reference)
#include <cuda_runtime.h>
#include <cuda_fp16.h>
#include <math.h>
#include <stdint.h>

// Problem constants
#define B_SZ   2
#define S_LEN  4096
#define HID    2048
#define Q_LR   768
#define KV_LR  512
#define QK_ROPE 64
#define QK_NOPE 128
#define HEADS  16
#define QK_HEAD 192
#define KV_HEAD 256
#define NTOK   (B_SZ * S_LEN)   // 8192
#define OUT_D  512

typedef __half fp16;

// ---------------------------------------------------------------------------
// Device scratch. fp16 planes in tiled SW128 layout:
// elem(m,k) -> tile (m>>7, k>>6) [tile = 8192 elems = 128 rows x 128B],
// row r=m&127, 16B chunk g=(k>>3)&7 stored at chunk (g ^ (r&7)).
// Down weights stacked: rows 0..767 = w_qa, rows 768..1343 = w_kva (pad 1536).
// ---------------------------------------------------------------------------
__device__ __align__(1024) fp16 g_hid_hi  [NTOK * HID];
__device__ __align__(1024) fp16 g_wdown_hi[1536 * HID];
__device__ __align__(1024) fp16 g_wqb_hi  [3072 * Q_LR];
__device__ __align__(1024) fp16 g_wkvb_hi [4096 * KV_LR];
__device__ __align__(1024) fp16 g_qln_hi  [NTOK * Q_LR];
__device__ __align__(1024) fp16 g_kvln_hi [NTOK * KV_LR];
__device__ float g_qc [NTOK * Q_LR];
__device__ float g_kvc[NTOK * (KV_LR + QK_ROPE)];
__device__ float g_cos[S_LEN * 32];
__device__ float g_sin[S_LEN * 32];

__device__ __forceinline__ size_t pidx(int m, int k, int K) {
    size_t tile = (size_t)((m >> 7) * (K >> 6) + (k >> 6)) * 8192;
    int r = m & 127;
    int g = (k >> 3) & 7;
    return tile + r * 64 + ((g ^ (r & 7)) << 3) + (k & 7);
}

// ---------------------------------------------------------------------------
__global__ void rope_table_kernel(float* __restrict__ ct, float* __restrict__ st) {
    int idx = blockIdx.x * blockDim.x + threadIdx.x;
    if (idx >= S_LEN * 32) return;
    int s = idx >> 5;
    int f = idx & 31;
    double inv = exp(-(double)f * (log(10000.0) / 32.0));
    double fr = (double)s * inv;
    ct[idx] = (float)cos(fr);
    st[idx] = (float)sin(fr);
}

// ---------------------------------------------------------------------------
// Pack fp32 [M,K] -> hi fp16 tiled plane at row offset moff (moff % 128 == 0)
// ---------------------------------------------------------------------------
__global__ void pack1(const float* __restrict__ src, fp16* __restrict__ hi,
                      int M, int Mpad, int K, int moff)
{
    long long c = (long long)blockIdx.x * blockDim.x + threadIdx.x;
    long long nch = (long long)Mpad * (K >> 3);
    if (c >= nch) return;
    int kc = (int)(c % (K >> 3));
    int m  = (int)(c / (K >> 3));
    int k0 = kc << 3;
    fp16 h[8];
#pragma unroll
    for (int j = 0; j < 8; j++) {
        float v = (m < M) ? src[(size_t)m * K + k0 + j] : 0.f;
        h[j] = __float2half_rn(v);
    }
    *(uint4*)(hi + pidx(m + moff, k0, K)) = *(uint4*)h;
}

// ---------------------------------------------------------------------------
// LayerNorm + pack into fp16 hi plane (row-per-block, row = blockIdx.x + moff)
// ---------------------------------------------------------------------------
__global__ __launch_bounds__(256)
void ln_pack(const float* __restrict__ in, int ld, int ncols,
             const float* __restrict__ gamma, const float* __restrict__ beta,
             fp16* __restrict__ hi, int moff)
{
    __shared__ float row[768];
    __shared__ float red[8];
    int m = blockIdx.x + moff;
    int tid = threadIdx.x;
    const float* src = in + (size_t)m * ld;

    float lsum = 0.f;
    for (int c = tid; c < ncols; c += 256) { float v = src[c]; row[c] = v; lsum += v; }
#pragma unroll
    for (int o = 16; o; o >>= 1) lsum += __shfl_xor_sync(0xffffffffu, lsum, o);
    if ((tid & 31) == 0) red[tid >> 5] = lsum;
    __syncthreads();
    float tot = 0.f;
#pragma unroll
    for (int i = 0; i < 8; i++) tot += red[i];
    float mu = tot / (float)ncols;
    __syncthreads();

    float lsq = 0.f;
    for (int c = tid; c < ncols; c += 256) { float d = row[c] - mu; lsq += d * d; }
#pragma unroll
    for (int o = 16; o; o >>= 1) lsq += __shfl_xor_sync(0xffffffffu, lsq, o);
    if ((tid & 31) == 0) red[tid >> 5] = lsq;
    __syncthreads();
    float tot2 = 0.f;
#pragma unroll
    for (int i = 0; i < 8; i++) tot2 += red[i];
    float inv = rsqrtf(tot2 / (float)ncols + 1e-5f);

    int nch = ncols >> 3;
    for (int ch = tid; ch < nch; ch += 256) {
        int c0 = ch << 3;
        fp16 h[8];
#pragma unroll
        for (int j = 0; j < 8; j++) {
            int c = c0 + j;
            h[j] = __float2half_rn((row[c] - mu) * inv * gamma[c] + beta[c]);
        }
        *(uint4*)(hi + pidx(m, c0, ncols)) = *(uint4*)h;
    }
}

// ---------------------------------------------------------------------------
// PTX helpers
// ---------------------------------------------------------------------------
__device__ __forceinline__ void ldsm4(unsigned& r0, unsigned& r1, unsigned& r2,
                                      unsigned& r3, unsigned addr) {
    asm volatile("ldmatrix.sync.aligned.m8n8.x4.shared.b16 {%0,%1,%2,%3}, [%4];"
                 : "=r"(r0), "=r"(r1), "=r"(r2), "=r"(r3) : "r"(addr));
}
__device__ __forceinline__ void mma16(float* d, const unsigned* a, const unsigned* b) {
    asm volatile(
        "mma.sync.aligned.m16n8k16.row.col.f32.f16.f16.f32 "
        "{%0,%1,%2,%3},{%4,%5,%6,%7},{%8,%9},{%0,%1,%2,%3};"
        : "+f"(d[0]), "+f"(d[1]), "+f"(d[2]), "+f"(d[3])
        : "r"(a[0]), "r"(a[1]), "r"(a[2]), "r"(a[3]), "r"(b[0]), "r"(b[1]));
}
__device__ __forceinline__ void bulk_ld(unsigned dst, const void* src, unsigned mbar) {
    asm volatile(
        "cp.async.bulk.shared::cluster.global.mbarrier::complete_tx::bytes "
        "[%0], [%1], %2, [%3];"
        :: "r"(dst), "l"(src), "r"(16384u), "r"(mbar) : "memory");
}
__device__ __forceinline__ void mbar_init(unsigned mbar, unsigned cnt) {
    asm volatile("mbarrier.init.shared.b64 [%0], %1;" :: "r"(mbar), "r"(cnt) : "memory");
}
__device__ __forceinline__ void mbar_expect(unsigned mbar, unsigned bytes) {
    asm volatile("mbarrier.arrive.expect_tx.shared.b64 _, [%0], %1;"
                 :: "r"(mbar), "r"(bytes) : "memory");
}
__device__ __forceinline__ void mbar_arrive(unsigned mbar) {
    asm volatile("mbarrier.arrive.shared.b64 _, [%0];" :: "r"(mbar) : "memory");
}
__device__ __forceinline__ void mbar_wait(unsigned mbar, unsigned phase) {
    asm volatile(
        "{\n\t.reg .pred P;\n\t"
        "W%=:\n\t"
        "mbarrier.try_wait.parity.acquire.cta.shared::cta.b64 P, [%0], %1, 0x989680;\n\t"
        "@P bra D%=;\n\t"
        "bra W%=;\n\t"
        "D%=:\n\t}"
        :: "r"(mbar), "r"(phase) : "memory");
}

// ---------------------------------------------------------------------------
// fp16 single-pass GEMM (NT): C = Ahi @ Bhi^T + bias
// CTA tile 128(M) x 256(N), k-block 64, 4-stage 48KB ring (Ah 16K | Bh 32K).
// 544 threads: 16 compute warps (warp tile 32x64) + 1 producer warp.
// m-tile = blockIdx.y + myoff (token-half pipelining).
// EPI 3: fused down-proj -> split store qc (n<768) / kvc (768<=n<1344)
// EPI 1: q up-proj + RoPE scatter.   EPI 2: kv up-proj scatter.
// ---------------------------------------------------------------------------
#define STAGE 49152u
#define NST 4
#define SMEM_TOTAL (NST * 49152 + 64)

template <int EPI>
__global__ __launch_bounds__(544, 1)
void gemm_hmma(const fp16* __restrict__ Ahi, const fp16* __restrict__ Bhi,
               const float* __restrict__ bias, float* __restrict__ out,
               int N, int K,
               const float* __restrict__ ctab, const float* __restrict__ stab,
               const float* __restrict__ bias2, float* __restrict__ out2,
               int myoff)
{
    extern __shared__ __align__(1024) char smem[];
    const unsigned sbase  = (unsigned)__cvta_generic_to_shared(smem);
    const unsigned fullb  = sbase + NST * STAGE;   // NST x 8B
    const unsigned emptyb = fullb + NST * 8;       // NST x 8B

    const int tid  = threadIdx.x;
    const int lane = tid & 31;
    const int wid  = tid >> 5;
    const int mtile = blockIdx.y + myoff;
    const int m0 = mtile * 128;
    const int n0 = blockIdx.x * 256;
    const int KB = K >> 6;
    const int ntile0 = n0 >> 7;

    if (tid == 0) {
#pragma unroll
        for (int s = 0; s < NST; s++) {
            mbar_init(fullb + s * 8, 1);
            mbar_init(emptyb + s * 8, 16);
        }
        asm volatile("fence.proxy.async.shared::cta;" ::: "memory");
    }
    __syncthreads();

    if (wid == 16) {
        // ---------------- producer warp ----------------
        if (lane == 0) {
            int eph[NST];
#pragma unroll
            for (int s = 0; s < NST; s++) eph[s] = 0;
            int st = 0;
            for (int kb = 0; kb < KB; kb++) {
                unsigned stg = sbase + st * STAGE;
                unsigned fb = fullb + st * 8;
                if (kb >= NST) { mbar_wait(emptyb + st * 8, eph[st]); eph[st] ^= 1; }
                mbar_expect(fb, STAGE);
                size_t aoff = ((size_t)mtile * KB + kb) * 8192;
                bulk_ld(stg, Ahi + aoff, fb);
                size_t b0 = ((size_t)ntile0 * KB + kb) * 8192;
                size_t b1 = ((size_t)(ntile0 + 1) * KB + kb) * 8192;
                bulk_ld(stg + 16384, Bhi + b0, fb);
                bulk_ld(stg + 32768, Bhi + b1, fb);
                if (++st == NST) st = 0;
            }
        }
        return;
    }

    // ---------------- compute warps ----------------
    const int wm = wid & 3;       // 0..3 along M (32 rows)
    const int wn = wid >> 2;      // 0..3 along N (64 cols)
    const int r = lane >> 2;
    const int c = lane & 3;

    float acc[2][8][4];
#pragma unroll
    for (int mt = 0; mt < 2; mt++)
#pragma unroll
        for (int nt = 0; nt < 8; nt++)
#pragma unroll
            for (int e = 0; e < 4; e++) acc[mt][nt][e] = 0.f;

    int fph[NST];
#pragma unroll
    for (int s = 0; s < NST; s++) fph[s] = 0;
    int st = 0;
    for (int kb = 0; kb < KB; kb++) {
        mbar_wait(fullb + st * 8, fph[st]);
        fph[st] ^= 1;
        const unsigned stage = sbase + st * STAGE;
#pragma unroll
        for (int t = 0; t < 4; t++) {
            unsigned ah[2][4];
            const int gA = t * 2 + (lane >> 4);
#pragma unroll
            for (int mt = 0; mt < 2; mt++) {
                int rowA = wm * 32 + mt * 16 + (lane & 15);
                unsigned off = stage + rowA * 128 + (((unsigned)(gA ^ (rowA & 7))) << 4);
                ldsm4(ah[mt][0], ah[mt][1], ah[mt][2], ah[mt][3], off);
            }
            const int gB = t * 2 + ((lane >> 3) & 1);
            const int rB = (lane & 7) + ((lane & 16) >> 1);
#pragma unroll
            for (int np = 0; np < 4; np++) {
                int rowB = wn * 64 + np * 16 + rB;
                unsigned off = stage + 16384 + ((rowB >> 7) << 14)
                             + (rowB & 127) * 128 + (((unsigned)(gB ^ (rowB & 7))) << 4);
                unsigned bh[4];
                ldsm4(bh[0], bh[1], bh[2], bh[3], off);
#pragma unroll
                for (int mt = 0; mt < 2; mt++) {
                    mma16(acc[mt][2 * np],     ah[mt], bh);
                    mma16(acc[mt][2 * np + 1], ah[mt], bh + 2);
                }
            }
        }
        if (lane == 0) mbar_arrive(emptyb + st * 8);
        if (++st == NST) st = 0;
    }

    // ---- bias (EPI 1/2: direct; EPI 3 handles bias inline) ----
    if (EPI != 3) {
#pragma unroll
        for (int nt = 0; nt < 8; nt++) {
            int nb = n0 + wn * 64 + nt * 8 + 2 * c;
            float b0 = bias[nb];
            float b1 = bias[nb + 1];
#pragma unroll
            for (int mt = 0; mt < 2; mt++) {
                acc[mt][nt][0] += b0; acc[mt][nt][1] += b1;
                acc[mt][nt][2] += b0; acc[mt][nt][3] += b1;
            }
        }
    }

    // ---- epilogue ----
    if (EPI == 3) {
        // fused down-proj split: n<768 -> qc[m,768], 768<=n<1344 -> kvc[m,576]
        const int nwb = n0 + wn * 64;          // 64-aligned, uniform per warp
        if (nwb < 1344) {
            const bool isq = (nwb < 768);
            float* dst0 = isq ? out : out2;
            const float* bsrc = isq ? bias : bias2;
            const int ldd = isq ? 768 : 576;
            const int ncol = isq ? nwb : (nwb - 768);
#pragma unroll
            for (int mt = 0; mt < 2; mt++)
#pragma unroll
                for (int half = 0; half < 2; half++) {
                    int m = m0 + wm * 32 + mt * 16 + r + half * 8;
#pragma unroll
                    for (int nt = 0; nt < 8; nt++) {
                        int nn = ncol + nt * 8 + 2 * c;
                        float v0 = acc[mt][nt][half * 2]     + bsrc[nn];
                        float v1 = acc[mt][nt][half * 2 + 1] + bsrc[nn + 1];
                        *(float2*)(dst0 + (size_t)m * ldd + nn) = make_float2(v0, v1);
                    }
                }
        }
    } else if (EPI == 1) {
#pragma unroll
        for (int mt = 0; mt < 2; mt++)
#pragma unroll
            for (int half = 0; half < 2; half++) {
                int m = m0 + wm * 32 + mt * 16 + r + half * 8;
                int s = m & (S_LEN - 1);
                int bb = m >> 12;
#pragma unroll
                for (int nt = 0; nt < 8; nt++) {
                    int n_base = n0 + wn * 64 + nt * 8;
                    int h = ((n_base >> 6) * 43) >> 7;          // /192
                    int d0 = n_base - h * 192 + 2 * c;
                    size_t obase = (((size_t)(bb * HEADS + h)) * S_LEN + s) * OUT_D;
                    float v0 = acc[mt][nt][half * 2];
                    float v1 = acc[mt][nt][half * 2 + 1];
                    if (d0 >= 128) {
                        int fi = d0 & 31;
                        float c0 = ctab[s * 32 + fi],     s0 = stab[s * 32 + fi];
                        float c1 = ctab[s * 32 + fi + 1], s1 = stab[s * 32 + fi + 1];
                        float p0 = acc[mt][nt ^ 4][half * 2];
                        float p1 = acc[mt][nt ^ 4][half * 2 + 1];
                        float sg = (d0 & 32) ? 1.f : -1.f;
                        v0 = v0 * c0 + sg * p0 * s0;
                        v1 = v1 * c1 + sg * p1 * s1;
                    }
                    *(float2*)(out + obase + d0) = make_float2(v0, v1);
                }
            }
    } else {
#pragma unroll
        for (int mt = 0; mt < 2; mt++)
#pragma unroll
            for (int half = 0; half < 2; half++) {
                int m = m0 + wm * 32 + mt * 16 + r + half * 8;
                int s = m & (S_LEN - 1);
                int bb = m >> 12;
#pragma unroll
                for (int nt = 0; nt < 8; nt++) {
                    int n_base = n0 + wn * 64 + nt * 8;
                    int h = n_base >> 8;
                    int d = (n_base & 255) + 2 * c;
                    int off = (d < 128) ? (192 + d) : (256 + d);
                    size_t obase = (((size_t)(bb * HEADS + h)) * S_LEN + s) * OUT_D;
                    *(float2*)(out + obase + off) =
                        make_float2(acc[mt][nt][half * 2], acc[mt][nt][half * 2 + 1]);
                }
            }
    }
}

// ---------------------------------------------------------------------------
// k_rot: RoPE on kv_c[:, 512:576] (pre-LN), broadcast to all 16 heads
// ---------------------------------------------------------------------------
__global__ void krot_kernel(const float* __restrict__ kvc,
                            const float* __restrict__ ctab,
                            const float* __restrict__ stab,
                            float* __restrict__ out, int toff)
{
    int t = blockIdx.x + toff;
    int d = threadIdx.x;
    int s = t & (S_LEN - 1);
    int bb = t >> 12;
    const float* kr = kvc + (size_t)t * (KV_LR + QK_ROPE) + KV_LR;
    float x = kr[d];
    float p = kr[d ^ 32];
    int fidx = d & 31;
    float cv = ctab[s * 32 + fidx];
    float sv = stab[s * 32 + fidx];
    float res = x * cv + ((d < 32) ? -p : p) * sv;
#pragma unroll
    for (int h = 0; h < HEADS; h++)
        out[(((size_t)bb * HEADS + h) * S_LEN + s) * OUT_D + 320 + d] = res;
}

// ---------------------------------------------------------------------------
extern "C" void kernel_launch(void* const* d_in, const int* in_sizes, int n_in,
                              void* d_out, int out_size)
{
    const float* hidden  = (const float*)d_in[0];
    const float* w_qa    = (const float*)d_in[1];
    const float* b_qa    = (const float*)d_in[2];
    const float* g_qa_ln = (const float*)d_in[3];
    const float* b_qa_ln = (const float*)d_in[4];
    const float* w_qb    = (const float*)d_in[5];
    const float* b_qb    = (const float*)d_in[6];
    const float* w_kva   = (const float*)d_in[7];
    const float* b_kva   = (const float*)d_in[8];
    const float* g_kva_ln= (const float*)d_in[9];
    const float* b_kva_ln= (const float*)d_in[10];
    const float* w_kvb   = (const float*)d_in[11];
    const float* b_kvb   = (const float*)d_in[12];
    float* out = (float*)d_out;

    fp16 *hid_hi, *wdown_hi, *wqb_hi, *wkvb_hi, *qln_hi, *kvln_hi;
    float *qc, *kvc, *ct, *st;
    cudaGetSymbolAddress((void**)&hid_hi,   g_hid_hi);
    cudaGetSymbolAddress((void**)&wdown_hi, g_wdown_hi);
    cudaGetSymbolAddress((void**)&wqb_hi,   g_wqb_hi);
    cudaGetSymbolAddress((void**)&wkvb_hi,  g_wkvb_hi);
    cudaGetSymbolAddress((void**)&qln_hi,   g_qln_hi);
    cudaGetSymbolAddress((void**)&kvln_hi,  g_kvln_hi);
    cudaGetSymbolAddress((void**)&qc,  g_qc);
    cudaGetSymbolAddress((void**)&kvc, g_kvc);
    cudaGetSymbolAddress((void**)&ct,  g_cos);
    cudaGetSymbolAddress((void**)&st,  g_sin);

    static cudaStream_t s1 = nullptr, s2 = nullptr, s3 = nullptr;
    static cudaEvent_t evA, evB, evD0, evD1, ev1, ev2, ev3;
    if (!s1) {
        cudaStreamCreateWithFlags(&s1, cudaStreamNonBlocking);
        cudaStreamCreateWithFlags(&s2, cudaStreamNonBlocking);
        cudaStreamCreateWithFlags(&s3, cudaStreamNonBlocking);
        cudaEventCreateWithFlags(&evA,  cudaEventDisableTiming);
        cudaEventCreateWithFlags(&evB,  cudaEventDisableTiming);
        cudaEventCreateWithFlags(&evD0, cudaEventDisableTiming);
        cudaEventCreateWithFlags(&evD1, cudaEventDisableTiming);
        cudaEventCreateWithFlags(&ev1,  cudaEventDisableTiming);
        cudaEventCreateWithFlags(&ev2,  cudaEventDisableTiming);
        cudaEventCreateWithFlags(&ev3,  cudaEventDisableTiming);
        cudaFuncSetAttribute((const void*)gemm_hmma<3>, cudaFuncAttributeMaxDynamicSharedMemorySize, SMEM_TOTAL);
        cudaFuncSetAttribute((const void*)gemm_hmma<1>, cudaFuncAttributeMaxDynamicSharedMemorySize, SMEM_TOTAL);
        cudaFuncSetAttribute((const void*)gemm_hmma<2>, cudaFuncAttributeMaxDynamicSharedMemorySize, SMEM_TOTAL);
    }

    // ---- fork s1: up-projection weight packs + rope table (indep of down path)
    cudaEventRecord(evA, 0);
    cudaStreamWaitEvent(s1, evA, 0);
    {
        long long nch = (long long)3072 * (Q_LR >> 3);
        pack1<<<(unsigned)((nch + 255) / 256), 256, 0, s1>>>(w_qb, wqb_hi, 3072, 3072, Q_LR, 0);
        nch = (long long)4096 * (KV_LR >> 3);
        pack1<<<(unsigned)((nch + 255) / 256), 256, 0, s1>>>(w_kvb, wkvb_hi, 4096, 4096, KV_LR, 0);
        rope_table_kernel<<<(S_LEN * 32 + 255) / 256, 256, 0, s1>>>(ct, st);
    }
    cudaEventRecord(evB, s1);

    // ---- stream 0: down path packs + fused down GEMM in two token halves
    {
        long long nch = (long long)NTOK * (HID >> 3);
        pack1<<<(unsigned)((nch + 255) / 256), 256>>>(hidden, hid_hi, NTOK, NTOK, HID, 0);
        nch = (long long)768 * (HID >> 3);
        pack1<<<(unsigned)((nch + 255) / 256), 256>>>(w_qa,  wdown_hi, 768, 768, HID, 0);
        pack1<<<(unsigned)((nch + 255) / 256), 256>>>(w_kva, wdown_hi, 576, 768, HID, 768);
    }
    gemm_hmma<3><<<dim3(6, 32), 544, SMEM_TOTAL>>>(hid_hi, wdown_hi,
                                                   b_qa, qc, 1536, HID,
                                                   nullptr, nullptr, b_kva, kvc, 0);
    cudaEventRecord(evD0, 0);
    gemm_hmma<3><<<dim3(6, 32), 544, SMEM_TOTAL>>>(hid_hi, wdown_hi,
                                                   b_qa, qc, 1536, HID,
                                                   nullptr, nullptr, b_kva, kvc, 32);
    cudaEventRecord(evD1, 0);

    // ---- half 0: q path on s2, kv path on s3 (overlap with down_h1)
    cudaStreamWaitEvent(s2, evD0, 0);
    ln_pack<<<4096, 256, 0, s2>>>(qc, Q_LR, Q_LR, g_qa_ln, b_qa_ln, qln_hi, 0);
    cudaStreamWaitEvent(s2, evB, 0);
    gemm_hmma<1><<<dim3(12, 32), 544, SMEM_TOTAL, s2>>>(qln_hi, wqb_hi,
                                                        b_qb, out, HEADS * QK_HEAD, Q_LR,
                                                        ct, st, nullptr, nullptr, 0);
    cudaEventRecord(ev2, s2);

    cudaStreamWaitEvent(s3, evD0, 0);
    ln_pack<<<4096, 256, 0, s3>>>(kvc, KV_LR + QK_ROPE, KV_LR, g_kva_ln, b_kva_ln, kvln_hi, 0);
    cudaStreamWaitEvent(s3, evB, 0);
    gemm_hmma<2><<<dim3(16, 32), 544, SMEM_TOTAL, s3>>>(kvln_hi, wkvb_hi,
                                                        b_kvb, out, HEADS * KV_HEAD, KV_LR,
                                                        nullptr, nullptr, nullptr, nullptr, 0);
    cudaEventRecord(ev3, s3);

    // ---- half 1: q path on stream 0, kv path + krot on s1
    ln_pack<<<4096, 256>>>(qc, Q_LR, Q_LR, g_qa_ln, b_qa_ln, qln_hi, 4096);
    cudaStreamWaitEvent(0, evB, 0);
    gemm_hmma<1><<<dim3(12, 32), 544, SMEM_TOTAL>>>(qln_hi, wqb_hi,
                                                    b_qb, out, HEADS * QK_HEAD, Q_LR,
                                                    ct, st, nullptr, nullptr, 32);

    cudaStreamWaitEvent(s1, evD0, 0);
    krot_kernel<<<4096, 64, 0, s1>>>(kvc, ct, st, out, 0);
    cudaStreamWaitEvent(s1, evD1, 0);
    krot_kernel<<<4096, 64, 0, s1>>>(kvc, ct, st, out, 4096);
    ln_pack<<<4096, 256, 0, s1>>>(kvc, KV_LR + QK_ROPE, KV_LR, g_kva_ln, b_kva_ln, kvln_hi, 4096);
    gemm_hmma<2><<<dim3(16, 32), 544, SMEM_TOTAL, s1>>>(kvln_hi, wkvb_hi,
                                                        b_kvb, out, HEADS * KV_HEAD, KV_LR,
                                                        nullptr, nullptr, nullptr, nullptr, 32);
    cudaEventRecord(ev1, s1);

    // ---- join all side streams back into stream 0
    cudaStreamWaitEvent(0, ev1, 0);
    cudaStreamWaitEvent(0, ev2, 0);
    cudaStreamWaitEvent(0, ev3, 0);
}